// round 14
// baseline (speedup 1.0000x reference)
#include <cuda_runtime.h>
#include <cuda_fp16.h>
#include <cstdint>

#define TT   128
#define SEQ  2048
#define NTOK 16384

// ---------------- device scratch ----------------
__device__ __align__(1024) __half g_Wh[TT * TT * TT];     // [t][p][q] fp16
__device__ __align__(1024) float  g_tokT[TT * NTOK];      // [p][tok]
__device__ float g_base[TT];

// ---------------- smem layout (bytes) ----------------
#define PITCH   272                 // 128 fp16 (256B) + 16B pad
#define BMAT    (128 * PITCH)       // 34816: one 128x128 fp16 matrix
#define NSTAGE  4
#define BC_OFF  (NSTAGE * BMAT)     // 139264
#define BV_OFF  (BC_OFF + 512)
#define SMEM_SZ (BV_OFF + 512)      // 140288

__device__ __forceinline__ uint32_t s2u(const void* p) {
    uint32_t a;
    asm("{ .reg .u64 t; cvta.to.shared.u64 t, %1; cvt.u32.u64 %0, t; }"
        : "=r"(a) : "l"(p));
    return a;
}
__device__ __forceinline__ void ldsm4(uint32_t* r, uint32_t a) {
    asm volatile("ldmatrix.sync.aligned.m8n8.x4.shared.b16 {%0,%1,%2,%3}, [%4];"
                 : "=r"(r[0]), "=r"(r[1]), "=r"(r[2]), "=r"(r[3]) : "r"(a));
}
__device__ __forceinline__ void mma16816(float* d, const uint32_t* a,
                                         const uint32_t* b, const float* c) {
    asm volatile(
        "mma.sync.aligned.m16n8k16.row.col.f32.f16.f16.f32 "
        "{%0,%1,%2,%3}, {%4,%5,%6,%7}, {%8,%9}, {%10,%11,%12,%13};"
        : "=f"(d[0]), "=f"(d[1]), "=f"(d[2]), "=f"(d[3])
        : "r"(a[0]), "r"(a[1]), "r"(a[2]), "r"(a[3]), "r"(b[0]), "r"(b[1]),
          "f"(c[0]), "f"(c[1]), "f"(c[2]), "f"(c[3]));
}
#define CP_COMMIT() asm volatile("cp.async.commit_group;" ::: "memory")
#define CP_WAIT(n)  asm volatile("cp.async.wait_group %0;" :: "n"(n) : "memory")

// load B_p (128 t-rows x 128 q fp16) into stage s; 8 cp.async per thread
__device__ __forceinline__ void load_B(uint32_t sb, int p, int s, int tid) {
#pragma unroll
    for (int it = 0; it < 8; ++it) {
        int item = tid + it * 256;             // 0..2047
        int row  = item >> 4;                  // t
        int seg  = item & 15;                  // 16B segment
        const __half* src = g_Wh + ((size_t)(row * TT + p)) * TT + seg * 8;
        uint32_t dst = sb + s * BMAT + row * PITCH + seg * 16;
        asm volatile("cp.async.cg.shared.global [%0], [%1], 16;"
                     :: "r"(dst), "l"(src) : "memory");
    }
}

// ---------------------------------------------------------------------------
__global__ void prep_kernel(const float* __restrict__ b_comp,
                            const float* __restrict__ w_red,
                            const float* __restrict__ b_red) {
    __shared__ float red[128];
    float s = 0.0f;
    for (int j = threadIdx.x; j < SEQ; j += 128) s += w_red[j];
    red[threadIdx.x] = s;
    __syncthreads();
    for (int off = 64; off > 0; off >>= 1) {
        if (threadIdx.x < off) red[threadIdx.x] += red[threadIdx.x + off];
        __syncthreads();
    }
    g_base[threadIdx.x] = red[0] * tanhf(b_comp[threadIdx.x]) + b_red[0];
}

__global__ void fill_kernel(float4* __restrict__ out4) {
    int i = blockIdx.x * 256 + threadIdx.x;
    int t4 = (i & 31) << 2;
    out4[i] = make_float4(g_base[t4], g_base[t4 + 1], g_base[t4 + 2], g_base[t4 + 3]);
}

__global__ void wsplit_kernel(const float* __restrict__ W) {
    int i = blockIdx.x * 256 + threadIdx.x;
    g_Wh[i] = __float2half_rn(W[i]);
}

__global__ void tokT_kernel(const float* __restrict__ token) {
    __shared__ float tile[32][33];
    const int t0 = blockIdx.x * 32;
    const int p0 = blockIdx.y * 32;
    for (int r = threadIdx.y; r < 32; r += 8)
        tile[r][threadIdx.x] = token[(size_t)(t0 + r) * TT + p0 + threadIdx.x];
    __syncthreads();
    for (int r = threadIdx.y; r < 32; r += 8)
        g_tokT[(size_t)(p0 + r) * NTOK + t0 + threadIdx.x] = tile[threadIdx.x][r];
}

// ---------------------------------------------------------------------------
__global__ __launch_bounds__(256, 1) void main_kernel(
    const float* __restrict__ token,
    const int*   __restrict__ heads,
    const float* __restrict__ b_comp,
    const float* __restrict__ w_red,
    float*       __restrict__ out) {
    extern __shared__ char smem[];
    const uint32_t sb = s2u(smem);
    const int tid  = threadIdx.x;
    const int wid  = tid >> 5;
    const int lane = tid & 31;
    const int g    = lane >> 2;
    const int tig  = lane & 3;
    const int mg   = wid & 3;                  // 4 m-groups
    const int ng   = wid >> 2;                 // 2 n-groups
    const int m0   = mg * 32;                  // warp's 32 token rows
    const int n0   = ng * 64;                  // warp's 64 output cols
    const int tok0 = blockIdx.x * 128;

    // ---- prologue: h = tanh(token) fp16, staged in stage 0 ----
    const float4* tk4 = (const float4*)(token + (size_t)tok0 * TT);
    for (int i = tid; i < 128 * 32; i += 256) {
        float4 v = tk4[i];
        int tok = i >> 5;
        int q4  = (i & 31) << 2;
        __half h0 = __float2half_rn(tanhf(v.x));
        __half h1 = __float2half_rn(tanhf(v.y));
        __half h2 = __float2half_rn(tanhf(v.z));
        __half h3 = __float2half_rn(tanhf(v.w));
        uint2 hv;
        hv.x = ((uint32_t)*(uint16_t*)&h1 << 16) | *(uint16_t*)&h0;
        hv.y = ((uint32_t)*(uint16_t*)&h3 << 16) | *(uint16_t*)&h2;
        *(uint2*)(smem + tok * PITCH + q4 * 2) = hv;
    }
    if (tid < 128) {
        float bc = b_comp[tid];
        ((float*)(smem + BC_OFF))[tid] = bc;
        ((float*)(smem + BV_OFF))[tid] = tanhf(bc);
    }
    __syncthreads();

    // ---- A fragments (2 m16 tiles), persistent in registers ----
    uint32_t a[2][8][4];
    {
        const int aro  = (lane & 7) + ((lane >> 3) & 1) * 8;
        const int acol = (lane >> 4) * 16;
#pragma unroll
        for (int mt = 0; mt < 2; ++mt)
#pragma unroll
            for (int kk = 0; kk < 8; ++kk)
                ldsm4(a[mt][kk], sb + (m0 + mt * 16 + aro) * PITCH + kk * 32 + acol);
    }
    __syncthreads();   // stage 0 may now be overwritten by B

    float val[2][32];
#pragma unroll
    for (int mt = 0; mt < 2; ++mt)
#pragma unroll
        for (int j = 0; j < 32; j++) val[mt][j] = 0.0f;
    const float z4[4] = {0.f, 0.f, 0.f, 0.f};

    // prime 3 stages
    load_B(sb, 0, 0, tid); CP_COMMIT();
    load_B(sb, 1, 1, tid); CP_COMMIT();
    load_B(sb, 2, 2, tid); CP_COMMIT();

    const uint32_t brow_off = (n0 + (lane & 7)) * PITCH + (lane >> 3) * 16;

    for (int p = 0; p < 128; ++p) {
        const int s = p & 3;
        CP_WAIT(2);            // group p complete
        __syncthreads();       // also guards stage (p+3)%4 reuse (read at p-1)

        const float* tkp = g_tokT + (size_t)p * NTOK + tok0 + m0;
        const float tk0L = tkp[g],      tk0H = tkp[8 + g];
        const float tk1L = tkp[16 + g], tk1H = tkp[24 + g];
        const uint32_t bs = sb + s * BMAT;

#pragma unroll 4
        for (int nt = 0; nt < 8; ++nt) {
            // 4 independent accumulation chains, depth 4 each
            float u0a[4], u0b[4], u1a[4], u1b[4];
            const uint32_t bbase = bs + nt * (8 * PITCH) + brow_off;
            uint32_t b[4];

            ldsm4(b, bbase + 0 * 64);                 // kk2 = 0 -> a-chains
            mma16816(u0a, a[0][0], b + 0, z4);
            mma16816(u1a, a[1][0], b + 0, z4);
            mma16816(u0a, a[0][1], b + 2, u0a);
            mma16816(u1a, a[1][1], b + 2, u1a);

            ldsm4(b, bbase + 1 * 64);                 // kk2 = 1 -> b-chains
            mma16816(u0b, a[0][2], b + 0, z4);
            mma16816(u1b, a[1][2], b + 0, z4);
            mma16816(u0b, a[0][3], b + 2, u0b);
            mma16816(u1b, a[1][3], b + 2, u1b);

            ldsm4(b, bbase + 2 * 64);                 // kk2 = 2 -> a-chains
            mma16816(u0a, a[0][4], b + 0, u0a);
            mma16816(u1a, a[1][4], b + 0, u1a);
            mma16816(u0a, a[0][5], b + 2, u0a);
            mma16816(u1a, a[1][5], b + 2, u1a);

            ldsm4(b, bbase + 3 * 64);                 // kk2 = 3 -> b-chains
            mma16816(u0b, a[0][6], b + 0, u0b);
            mma16816(u1b, a[1][6], b + 0, u1b);
            mma16816(u0b, a[0][7], b + 2, u0b);
            mma16816(u1b, a[1][7], b + 2, u1b);

#pragma unroll
            for (int e = 0; e < 4; ++e) {
                const float tk0 = (e < 2) ? tk0L : tk0H;
                const float tk1 = (e < 2) ? tk1L : tk1H;
                val[0][nt * 4 + e] = fmaf(tk0, u0a[e] + u0b[e], val[0][nt * 4 + e]);
                val[1][nt * 4 + e] = fmaf(tk1, u1a[e] + u1b[e], val[1][nt * 4 + e]);
            }
        }
        if (p + 3 < 128) { load_B(sb, p + 3, (p + 3) & 3, tid); CP_COMMIT(); }
    }

    // ---- epilogue: tanh + scatter-add into head rows ----
    const float* sBc = (const float*)(smem + BC_OFF);
    const float* sBv = (const float*)(smem + BV_OFF);
#pragma unroll
    for (int mt = 0; mt < 2; ++mt) {
#pragma unroll
        for (int half = 0; half < 2; ++half) {
            const int gtok = tok0 + m0 + mt * 16 + half * 8 + g;
            const int bI   = gtok >> 11;
            const int jseq = gtok & (SEQ - 1);
            const float ww = w_red[jseq];
            const int head = heads[gtok];
            float* orow = out + ((size_t)(bI * SEQ + head)) * TT;
            const int vo = half * 2;
#pragma unroll
            for (int nt = 0; nt < 8; ++nt) {
                const int c = n0 + nt * 8 + 2 * tig;
                float a0 = tanhf(val[mt][nt * 4 + vo + 0] + sBc[c]);
                float a1 = tanhf(val[mt][nt * 4 + vo + 1] + sBc[c + 1]);
                atomicAdd(orow + c,     ww * (a0 - sBv[c]));
                atomicAdd(orow + c + 1, ww * (a1 - sBv[c + 1]));
            }
        }
    }
}

// ---------------------------------------------------------------------------
extern "C" void kernel_launch(void* const* d_in, const int* in_sizes, int n_in,
                              void* d_out, int out_size) {
    const float* token  = (const float*)d_in[0];
    const int*   heads  = (const int*)d_in[2];
    const float* W      = (const float*)d_in[3];
    const float* b_comp = (const float*)d_in[4];
    const float* w_red  = (const float*)d_in[5];
    const float* b_red  = (const float*)d_in[6];
    float* out = (float*)d_out;

    prep_kernel<<<1, 128>>>(b_comp, w_red, b_red);
    fill_kernel<<<(NTOK * TT / 4) / 256, 256>>>((float4*)out);
    wsplit_kernel<<<(TT * TT * TT) / 256, 256>>>(W);
    tokT_kernel<<<dim3(NTOK / 32, TT / 32), dim3(32, 8)>>>(token);

    cudaFuncSetAttribute(main_kernel, cudaFuncAttributeMaxDynamicSharedMemorySize,
                         SMEM_SZ);
    main_kernel<<<NTOK / 128, 256, SMEM_SZ>>>(token, heads, b_comp, w_red, out);
}